// round 3
// baseline (speedup 1.0000x reference)
#include <cuda_runtime.h>
#include <math.h>

// Problem constants
#define B_   2
#define N_   2048
#define K_   48
#define D0_  64
#define D1_  64
#define H_   64
#define EIN_ 193
#define E2_  386   // 2*EIN
#define H4_  256   // 4*H

// Scratch (device globals -- no allocation allowed)
__device__ float g_mi[B_ * N_ * H_];        // 1 MB
__device__ float g_htu[B_ * N_ * D1_ * 3];  // 3 MB
__device__ int   g_mask_mode;               // 0=uint8, 1=int32, 2=float32

__device__ __forceinline__ float siluf(float v) { return v / (1.f + expf(-v)); }

// Detect how the bool mask array was materialized on device.
// bool->uint8: dense 0/1 bytes. bool->int32: words are 0 or 1.
// bool->float32: words are 0 or 0x3F800000.
__global__ void detect_mask_kernel(const unsigned int* __restrict__ w) {
    bool int_ok = true, flt_ok = true;
    #pragma unroll 8
    for (int i = 0; i < 64; i++) {
        unsigned int v = w[i];
        if (v != 0u && v != 1u) int_ok = false;
        if (v != 0u && v != 0x3F800000u) flt_ok = false;
    }
    g_mask_mode = int_ok ? 1 : (flt_ok ? 2 : 0);
}

// Shared memory layout (floats)
#define OFF_NI   0          // 64   nodes_i
#define OFF_HTI  64         // 192  ht_i (64x3)
#define OFF_X    256        // 129*48 = 6192  x rows [nodes_j(64) | relhtdist(64) | reldist(1)], layout [i][k]
#define OFF_H1   6448       // 386*48 = 18528 h1 (post-silu), layout [o][k]
#define OFF_M    24976      // 64*48 = 3072   m_ij (post-silu), layout [h][k]
#define OFF_H3   28048      // 256*48 = 12288 h3 (post-silu), layout [g][k]
#define OFF_HTW  40336      // 64*48 = 3072   htw, layout [d][k]
#define OFF_RED  43408      // 8*192 = 1536   reduction buffer
#define OFF_HNS  44944      // 64
#define OFF_HNB  45008      // 64
#define OFF_MSK  45072      // 48
#define OFF_IDX  45120      // 48 ints
#define SMEM_FLOATS 45168   // 180,672 bytes

__global__ __launch_bounds__(512, 1) void edge_kernel(
    const float* __restrict__ f0, const float* __restrict__ f1,
    const float* __restrict__ rd, const int* __restrict__ nidx,
    const unsigned char* __restrict__ nmask,
    const float* __restrict__ eW1, const float* __restrict__ eb1,
    const float* __restrict__ eW2, const float* __restrict__ eb2,
    const float* __restrict__ hW1, const float* __restrict__ hb1,
    const float* __restrict__ hW2, const float* __restrict__ hb2,
    const float* __restrict__ hns, const float* __restrict__ hnb)
{
    extern __shared__ float sm[];
    const int node = blockIdx.x;          // b*N + n
    const int base = (node >> 11) << 11;  // b*N  (N=2048)
    const int tid = threadIdx.x;

    float* ni_s  = sm + OFF_NI;
    float* hti   = sm + OFF_HTI;
    float* x_s   = sm + OFF_X;
    float* h1_s  = sm + OFF_H1;
    float* m_s   = sm + OFF_M;
    float* h3_s  = sm + OFF_H3;
    float* htw_s = sm + OFF_HTW;
    float* red   = sm + OFF_RED;
    float* hns_s = sm + OFF_HNS;
    float* hnb_s = sm + OFF_HNB;
    float* msk_s = sm + OFF_MSK;
    int*   idx_s = (int*)(sm + OFF_IDX);

    // ---- Stage 0: per-node loads ----
    if (tid < 64) {
        ni_s[tid]  = f0[node * 64 + tid];
        hns_s[tid] = hns[tid];
        hnb_s[tid] = hnb[tid];
    }
    if (tid >= 64 && tid < 256) hti[tid - 64] = f1[node * 192 + (tid - 64)];
    if (tid >= 256 && tid < 304) {
        int k = tid - 256;
        idx_s[k] = nidx[node * 48 + k];
        int mode = g_mask_mode;
        float mv;
        if (mode == 1)      mv = ((const int*)nmask)[node * 48 + k] ? 1.f : 0.f;
        else if (mode == 2) mv = ((const float*)nmask)[node * 48 + k];
        else                mv = nmask[node * 48 + k] ? 1.f : 0.f;
        msk_s[k] = mv;
        x_s[128 * 48 + k] = rd[node * 48 + k];
    }
    __syncthreads();

    // ---- Stage 1: build x rows (nodes_j, rel_ht_dist) ----
    for (int e = tid; e < 48 * 64; e += 512) {
        int k = e >> 6, d = e & 63;
        int j = base + idx_s[k];
        x_s[d * 48 + k] = f0[j * 64 + d];
        const float* hj = f1 + j * 192 + d * 3;
        float r0 = hti[d * 3 + 0] - hj[0];
        float r1 = hti[d * 3 + 1] - hj[1];
        float r2 = hti[d * 3 + 2] - hj[2];
        x_s[(64 + d) * 48 + k] = sqrtf(r0 * r0 + r1 * r1 + r2 * r2);
    }
    __syncthreads();

    // ---- GEMM1: h1[k][o] = silu( c0[o] + sum_i x[k][i]*eW1[64+i][o] ) ----
    {
        int ob = tid & 127;
        int k0 = (tid >> 7) * 12;
        for (int oi = 0; oi < 4; oi++) {
            int o = ob + oi * 128;
            if (o >= E2_) break;
            // c0: bias + nodes_i contribution (rows 0..63 of eW1), identical for all k
            float c0 = eb1[o];
            #pragma unroll 4
            for (int i = 0; i < 64; i++) c0 += ni_s[i] * eW1[i * E2_ + o];
            float acc[12];
            #pragma unroll
            for (int kk = 0; kk < 12; kk++) acc[kk] = c0;
            const float* wcol = eW1 + 64 * E2_ + o;
            #pragma unroll 4
            for (int i = 0; i < 129; i++) {
                float w = wcol[i * E2_];
                const float4* xr = (const float4*)(x_s + i * 48 + k0);
                float4 a0 = xr[0], a1 = xr[1], a2 = xr[2];
                acc[0]  += w * a0.x; acc[1]  += w * a0.y; acc[2]  += w * a0.z; acc[3]  += w * a0.w;
                acc[4]  += w * a1.x; acc[5]  += w * a1.y; acc[6]  += w * a1.z; acc[7]  += w * a1.w;
                acc[8]  += w * a2.x; acc[9]  += w * a2.y; acc[10] += w * a2.z; acc[11] += w * a2.w;
            }
            #pragma unroll
            for (int kk = 0; kk < 12; kk++) h1_s[o * 48 + k0 + kk] = siluf(acc[kk]);
        }
    }
    __syncthreads();

    // ---- GEMM2: m[k][h] = silu( eb2[h] + sum_o h1[k][o]*eW2[o][h] ) ----
    {
        int h = tid & 63;
        int k0 = (tid >> 6) * 6;
        float b0 = eb2[h];
        float acc[6];
        #pragma unroll
        for (int kk = 0; kk < 6; kk++) acc[kk] = b0;
        #pragma unroll 4
        for (int o = 0; o < E2_; o++) {
            float w = eW2[o * 64 + h];
            const float2* hr = (const float2*)(h1_s + o * 48 + k0);
            float2 a0 = hr[0], a1 = hr[1], a2 = hr[2];
            acc[0] += w * a0.x; acc[1] += w * a0.y;
            acc[2] += w * a1.x; acc[3] += w * a1.y;
            acc[4] += w * a2.x; acc[5] += w * a2.y;
        }
        #pragma unroll
        for (int kk = 0; kk < 6; kk++) m_s[h * 48 + k0 + kk] = siluf(acc[kk]);
    }
    __syncthreads();

    // ---- GEMM3: h3[k][g] = silu( hb1[g] + sum_h m[k][h]*hW1[h][g] ) ----
    {
        int gb_ = tid & 127;
        int k0 = (tid >> 7) * 12;
        for (int gi = 0; gi < 2; gi++) {
            int g = gb_ + gi * 128;
            float b0 = hb1[g];
            float acc[12];
            #pragma unroll
            for (int kk = 0; kk < 12; kk++) acc[kk] = b0;
            #pragma unroll 4
            for (int h = 0; h < 64; h++) {
                float w = hW1[h * H4_ + g];
                const float4* xr = (const float4*)(m_s + h * 48 + k0);
                float4 a0 = xr[0], a1 = xr[1], a2 = xr[2];
                acc[0]  += w * a0.x; acc[1]  += w * a0.y; acc[2]  += w * a0.z; acc[3]  += w * a0.w;
                acc[4]  += w * a1.x; acc[5]  += w * a1.y; acc[6]  += w * a1.z; acc[7]  += w * a1.w;
                acc[8]  += w * a2.x; acc[9]  += w * a2.y; acc[10] += w * a2.z; acc[11] += w * a2.w;
            }
            #pragma unroll
            for (int kk = 0; kk < 12; kk++) h3_s[g * 48 + k0 + kk] = siluf(acc[kk]);
        }
    }
    __syncthreads();

    // ---- GEMM4: htw[k][d] = hb2[d] + sum_g h3[k][g]*hW2[g][d] ----
    {
        int d = tid & 63;
        int k0 = (tid >> 6) * 6;
        float b0 = hb2[d];
        float acc[6];
        #pragma unroll
        for (int kk = 0; kk < 6; kk++) acc[kk] = b0;
        #pragma unroll 4
        for (int g = 0; g < H4_; g++) {
            float w = hW2[g * 64 + d];
            const float2* hr = (const float2*)(h3_s + g * 48 + k0);
            float2 a0 = hr[0], a1 = hr[1], a2 = hr[2];
            acc[0] += w * a0.x; acc[1] += w * a0.y;
            acc[2] += w * a1.x; acc[3] += w * a1.y;
            acc[4] += w * a2.x; acc[5] += w * a2.y;
        }
        #pragma unroll
        for (int kk = 0; kk < 6; kk++) htw_s[d * 48 + k0 + kk] = acc[kk];
    }
    __syncthreads();

    // ---- m_i = sum_k mask[k] * m_ij[k][h] ----
    {
        int h = tid & 63;
        int kb = tid >> 6;
        int k0 = kb * 6;
        float s = 0.f;
        #pragma unroll
        for (int kk = 0; kk < 6; kk++) s += msk_s[k0 + kk] * m_s[h * 48 + k0 + kk];
        red[kb * 64 + h] = s;
    }
    __syncthreads();
    if (tid < 64) {
        float s = 0.f;
        #pragma unroll
        for (int kb = 0; kb < 8; kb++) s += red[kb * 64 + tid];
        g_mi[node * 64 + tid] = s;
    }
    __syncthreads();

    // ---- ht_update einsum: recompute rel_ht via gather (L2-hit), accumulate over k ----
    {
        int d = tid & 63;
        int kb = tid >> 6;
        int k0 = kb * 6;
        float a0 = 0.f, a1 = 0.f, a2 = 0.f;
        float sc = hns_s[d], bi = hnb_s[d];
        float h0 = hti[d * 3 + 0], h1v = hti[d * 3 + 1], h2 = hti[d * 3 + 2];
        #pragma unroll
        for (int kk = 0; kk < 6; kk++) {
            int k = k0 + kk;
            int j = base + idx_s[k];
            const float* hj = f1 + j * 192 + d * 3;
            float r0 = h0 - hj[0];
            float r1 = h1v - hj[1];
            float r2 = h2 - hj[2];
            float nrm = sqrtf(r0 * r0 + r1 * r1 + r2 * r2);
            float coef = (nrm * sc + bi) / fmaxf(nrm, 1e-8f);
            float w = coef * htw_s[d * 48 + k];
            a0 += r0 * w; a1 += r1 * w; a2 += r2 * w;
        }
        red[kb * 192 + d * 3 + 0] = a0;
        red[kb * 192 + d * 3 + 1] = a1;
        red[kb * 192 + d * 3 + 2] = a2;
    }
    __syncthreads();
    if (tid < 192) {
        float s = 0.f;
        #pragma unroll
        for (int kb = 0; kb < 8; kb++) s += red[kb * 192 + tid];
        g_htu[node * 192 + tid] = s;
    }
}

// ---- Node update: LayerNorm -> MLP(128->128->64) + residual -> gate -> assemble ----
__global__ __launch_bounds__(128) void node_kernel(
    const float* __restrict__ f0, const float* __restrict__ f1,
    const float* __restrict__ ln_g, const float* __restrict__ ln_b,
    const float* __restrict__ nW1, const float* __restrict__ nb1,
    const float* __restrict__ nW2, const float* __restrict__ nb2,
    const float* __restrict__ gW, const float* __restrict__ gb,
    float* __restrict__ out)
{
    __shared__ float nodes_s[64], nm[128], hbuf[128], no_s[64], stat[2];
    const int node = blockIdx.x;
    const int t = threadIdx.x;

    if (t < 64) {
        nodes_s[t] = f0[node * 64 + t];
        nm[64 + t] = g_mi[node * 64 + t];
    }
    __syncthreads();

    if (t < 32) {
        float s = nodes_s[t] + nodes_s[t + 32];
        #pragma unroll
        for (int off = 16; off > 0; off >>= 1) s += __shfl_xor_sync(0xffffffffu, s, off);
        if (t == 0) stat[0] = s * (1.f / 64.f);
    }
    __syncthreads();
    float mu = stat[0];
    if (t < 32) {
        float d0 = nodes_s[t] - mu, d1 = nodes_s[t + 32] - mu;
        float s = d0 * d0 + d1 * d1;
        #pragma unroll
        for (int off = 16; off > 0; off >>= 1) s += __shfl_xor_sync(0xffffffffu, s, off);
        if (t == 0) stat[1] = s * (1.f / 64.f);
    }
    __syncthreads();
    float inv = rsqrtf(stat[1] + 1e-5f);
    if (t < 64) nm[t] = (nodes_s[t] - mu) * inv * ln_g[t] + ln_b[t];
    __syncthreads();

    // layer 1: 128 -> 128
    {
        float a = nb1[t];
        #pragma unroll 4
        for (int e = 0; e < 128; e++) a += nm[e] * nW1[e * 128 + t];
        hbuf[t] = siluf(a);
    }
    __syncthreads();

    // layer 2: 128 -> 64, + residual
    if (t < 64) {
        float a = nb2[t];
        #pragma unroll 4
        for (int g = 0; g < 128; g++) a += hbuf[g] * nW2[g * 64 + t];
        no_s[t] = a + nodes_s[t];
    }
    __syncthreads();

    if (t < 64) {
        float a = gb[t];
        #pragma unroll 4
        for (int e = 0; e < 64; e++) a += no_s[e] * gW[e * 64 + t];
        float gate = 1.f / (1.f + expf(-a));
        int ob = node * 256 + t * 4;
        out[ob + 0] = no_s[t];
        #pragma unroll
        for (int m = 0; m < 3; m++)
            out[ob + 1 + m] = (f1[node * 192 + t * 3 + m] + g_htu[node * 192 + t * 3 + m]) * gate;
    }
}

extern "C" void kernel_launch(void* const* d_in, const int* in_sizes, int n_in,
                              void* d_out, int out_size)
{
    const float*         f0    = (const float*)d_in[0];   // features0 (B,N,64,1)
    const float*         f1    = (const float*)d_in[1];   // features1 (B,N,64,3)
    const float*         rd    = (const float*)d_in[2];   // rel_dist  (B,N,K)
    const int*           nidx  = (const int*)d_in[3];     // neighbor_indices
    const unsigned char* nmask = (const unsigned char*)d_in[4]; // neighbor_masks (bool)
    const float* ln_g = (const float*)d_in[5];
    const float* ln_b = (const float*)d_in[6];
    const float* eW1  = (const float*)d_in[7];
    const float* eb1  = (const float*)d_in[8];
    const float* eW2  = (const float*)d_in[9];
    const float* eb2  = (const float*)d_in[10];
    const float* hW1  = (const float*)d_in[11];
    const float* hb1  = (const float*)d_in[12];
    const float* hW2  = (const float*)d_in[13];
    const float* hb2  = (const float*)d_in[14];
    const float* nW1  = (const float*)d_in[15];
    const float* nb1  = (const float*)d_in[16];
    const float* nW2  = (const float*)d_in[17];
    const float* nb2  = (const float*)d_in[18];
    const float* hns  = (const float*)d_in[19];
    const float* hnb  = (const float*)d_in[20];
    const float* gW   = (const float*)d_in[21];
    const float* gb   = (const float*)d_in[22];
    float* out = (float*)d_out;

    cudaFuncSetAttribute(edge_kernel, cudaFuncAttributeMaxDynamicSharedMemorySize,
                         SMEM_FLOATS * (int)sizeof(float));

    detect_mask_kernel<<<1, 1>>>((const unsigned int*)nmask);
    edge_kernel<<<B_ * N_, 512, SMEM_FLOATS * sizeof(float)>>>(
        f0, f1, rd, nidx, nmask, eW1, eb1, eW2, eb2, hW1, hb1, hW2, hb2, hns, hnb);
    node_kernel<<<B_ * N_, 128>>>(
        f0, f1, ln_g, ln_b, nW1, nb1, nW2, nb2, gW, gb, out);
}

// round 8
// speedup vs baseline: 1.1633x; 1.1633x over previous
#include <cuda_runtime.h>
#include <math.h>

typedef unsigned long long u64;

// Problem constants
#define B_   2
#define N_   2048
#define K_   48
#define D0_  64
#define D1_  64
#define H_   64
#define EIN_ 193
#define E2_  386   // 2*EIN
#define H4_  256   // 4*H

__device__ int g_mask_mode;  // 0=uint8, 1=int32, 2=float32

// Detect how the bool mask array was materialized on device.
__global__ void detect_mask_kernel(const unsigned int* __restrict__ w) {
    bool int_ok = true, flt_ok = true;
    #pragma unroll 8
    for (int i = 0; i < 64; i++) {
        unsigned int v = w[i];
        if (v != 0u && v != 1u) int_ok = false;
        if (v != 0u && v != 0x3F800000u) flt_ok = false;
    }
    g_mask_mode = int_ok ? 1 : (flt_ok ? 2 : 0);
}

__device__ __forceinline__ float siluf(float v) {
    return v * __fdividef(1.f, 1.f + __expf(-v));
}
__device__ __forceinline__ u64 dup2(float w) {
    u64 r; asm("mov.b64 %0, {%1, %1};" : "=l"(r) : "f"(w)); return r;
}
__device__ __forceinline__ void ffma2(u64 &d, u64 a, u64 b) {
    asm("fma.rn.f32x2 %0, %1, %2, %0;" : "+l"(d) : "l"(a), "l"(b));
}
__device__ __forceinline__ u64 addf2(u64 a, u64 b) {
    u64 r; asm("add.rn.f32x2 %0, %1, %2;" : "=l"(r) : "l"(a), "l"(b)); return r;
}
__device__ __forceinline__ float2 unpk(u64 v) {
    float2 f; asm("mov.b64 {%0, %1}, %2;" : "=f"(f.x), "=f"(f.y) : "l"(v)); return f;
}

// Shared memory layout (floats)
#define OFF_NI   0          // 64    nodes_i
#define OFF_HTI  64         // 192   ht_i (64x3)
#define OFF_X    256        // 129*48 = 6192  x rows, layout [i][k]  (reused as G4 partial + scratch)
#define OFF_H1   6448       // 386*48 = 18528 h1 (post-silu), [o][k]
#define OFF_M    24976      // 64*48 = 3072   m_ij (post-silu), [h][k]
#define OFF_H3   28048      // 256*48 = 12288 h3 (post-silu), [g][k]  (first used as G2 partial)
#define OFF_HTW  40336      // 64*48 = 3072   htw, [d][k]
#define OFF_RED  43408      // 8*192 = 1536   reduction buffer
#define OFF_HNS  44944      // 64
#define OFF_HNB  45008      // 64
#define OFF_MSK  45072      // 48
#define OFF_IDX  45120      // 48 ints
#define OFF_MI   45168      // 64    m_i
#define OFF_HTU  45232      // 192   ht_update
#define OFF_NM   45424      // 128   [normed_nodes | m_i] tail input
#define OFF_HB   45552      // 128   tail hidden
#define OFF_NO   45680      // 64    node_out
#define OFF_STAT 45744      // 2
#define SMEM_FLOATS 45760   // 183,040 bytes

__global__ __launch_bounds__(512, 1) void fused_kernel(
    const float* __restrict__ f0, const float* __restrict__ f1,
    const float* __restrict__ rd, const int* __restrict__ nidx,
    const unsigned char* __restrict__ nmask,
    const float* __restrict__ ln_g, const float* __restrict__ ln_b,
    const float* __restrict__ eW1, const float* __restrict__ eb1,
    const float* __restrict__ eW2, const float* __restrict__ eb2,
    const float* __restrict__ hW1, const float* __restrict__ hb1,
    const float* __restrict__ hW2, const float* __restrict__ hb2,
    const float* __restrict__ nW1, const float* __restrict__ nb1,
    const float* __restrict__ nW2, const float* __restrict__ nb2,
    const float* __restrict__ hns, const float* __restrict__ hnb,
    const float* __restrict__ gW, const float* __restrict__ gb,
    float* __restrict__ out)
{
    extern __shared__ float sm[];
    const int node = blockIdx.x;
    const int base = (node >> 11) << 11;
    const int tid = threadIdx.x;

    float* ni_s  = sm + OFF_NI;
    float* hti   = sm + OFF_HTI;
    float* x_s   = sm + OFF_X;
    float* h1_s  = sm + OFF_H1;
    float* m_s   = sm + OFF_M;
    float* h3_s  = sm + OFF_H3;
    float* htw_s = sm + OFF_HTW;
    float* red   = sm + OFF_RED;
    float* hns_s = sm + OFF_HNS;
    float* hnb_s = sm + OFF_HNB;
    float* msk_s = sm + OFF_MSK;
    int*   idx_s = (int*)(sm + OFF_IDX);
    float* mi_s  = sm + OFF_MI;
    float* htu_s = sm + OFF_HTU;
    float* nm    = sm + OFF_NM;
    float* hbuf  = sm + OFF_HB;
    float* no_s  = sm + OFF_NO;
    float* stat  = sm + OFF_STAT;

    // ---- Stage 0: per-node loads ----
    if (tid < 64) {
        ni_s[tid]  = f0[node * 64 + tid];
        hns_s[tid] = hns[tid];
        hnb_s[tid] = hnb[tid];
    }
    if (tid >= 64 && tid < 256) hti[tid - 64] = f1[node * 192 + (tid - 64)];
    if (tid >= 256 && tid < 304) {
        int k = tid - 256;
        idx_s[k] = nidx[node * 48 + k];
        int mode = g_mask_mode;
        float mv;
        if (mode == 1)      mv = ((const int*)nmask)[node * 48 + k] ? 1.f : 0.f;
        else if (mode == 2) mv = ((const float*)nmask)[node * 48 + k];
        else                mv = nmask[node * 48 + k] ? 1.f : 0.f;
        msk_s[k] = mv;
        x_s[128 * 48 + k] = rd[node * 48 + k];
    }
    __syncthreads();

    // ---- Stage 1: build x rows (nodes_j, rel_ht_dist) ----
    for (int e = tid; e < 48 * 64; e += 512) {
        int k = e >> 6, d = e & 63;
        int j = base + idx_s[k];
        x_s[d * 48 + k] = f0[j * 64 + d];
        const float* hj = f1 + j * 192 + d * 3;
        float r0 = hti[d * 3 + 0] - hj[0];
        float r1 = hti[d * 3 + 1] - hj[1];
        float r2 = hti[d * 3 + 2] - hj[2];
        x_s[(64 + d) * 48 + k] = sqrtf(r0 * r0 + r1 * r1 + r2 * r2);
    }
    __syncthreads();

    // ---- GEMM1: h1[o][k] = silu( c0[o] + sum_i x[i][k]*eW1[64+i][o] ) ----
    // thread: 3(+1) outputs {ob, ob+128, ob+256, (ob+384 if ob<2)} x 12 k (6 packed)
    {
        const int ob = tid & 127;
        const int k0 = (tid >> 7) * 12;
        const bool has4 = (ob < 2);

        float c0[4];
        c0[0] = eb1[ob]; c0[1] = eb1[ob + 128]; c0[2] = eb1[ob + 256];
        c0[3] = has4 ? eb1[ob + 384] : 0.f;
        #pragma unroll 4
        for (int i = 0; i < 64; i++) {
            float niv = ni_s[i];
            const float* wr = eW1 + i * E2_ + ob;
            c0[0] += niv * wr[0];
            c0[1] += niv * wr[128];
            c0[2] += niv * wr[256];
            if (has4) c0[3] += niv * wr[384];
        }

        u64 acc[3][6], acc4[6];
        #pragma unroll
        for (int oi = 0; oi < 3; oi++) {
            u64 d = dup2(c0[oi]);
            #pragma unroll
            for (int j = 0; j < 6; j++) acc[oi][j] = d;
        }
        {
            u64 d = dup2(c0[3]);
            #pragma unroll
            for (int j = 0; j < 6; j++) acc4[j] = d;
        }

        const float* xb = x_s + k0;
        for (int i = 0; i < 129; i++) {
            const ulonglong2* xr = (const ulonglong2*)(xb + i * 48);
            ulonglong2 A = xr[0], Bv = xr[1], C = xr[2];
            u64 a0 = A.x, a1 = A.y, a2 = Bv.x, a3 = Bv.y, a4 = C.x, a5 = C.y;
            const float* wr = eW1 + (64 + i) * E2_ + ob;
            #pragma unroll
            for (int oi = 0; oi < 3; oi++) {
                u64 w2 = dup2(wr[oi * 128]);
                ffma2(acc[oi][0], a0, w2); ffma2(acc[oi][1], a1, w2);
                ffma2(acc[oi][2], a2, w2); ffma2(acc[oi][3], a3, w2);
                ffma2(acc[oi][4], a4, w2); ffma2(acc[oi][5], a5, w2);
            }
            if (has4) {
                u64 w2 = dup2(wr[384]);
                ffma2(acc4[0], a0, w2); ffma2(acc4[1], a1, w2);
                ffma2(acc4[2], a2, w2); ffma2(acc4[3], a3, w2);
                ffma2(acc4[4], a4, w2); ffma2(acc4[5], a5, w2);
            }
        }

        #pragma unroll
        for (int oi = 0; oi < 3; oi++) {
            float* dst = h1_s + (ob + oi * 128) * 48 + k0;
            #pragma unroll
            for (int jj = 0; jj < 3; jj++) {
                float2 p0 = unpk(acc[oi][2 * jj]), p1 = unpk(acc[oi][2 * jj + 1]);
                float4 v = make_float4(siluf(p0.x), siluf(p0.y), siluf(p1.x), siluf(p1.y));
                ((float4*)dst)[jj] = v;
            }
        }
        if (has4) {
            float* dst = h1_s + (ob + 384) * 48 + k0;
            #pragma unroll
            for (int jj = 0; jj < 3; jj++) {
                float2 p0 = unpk(acc4[2 * jj]), p1 = unpk(acc4[2 * jj + 1]);
                float4 v = make_float4(siluf(p0.x), siluf(p0.y), siluf(p1.x), siluf(p1.y));
                ((float4*)dst)[jj] = v;
            }
        }
    }
    __syncthreads();

    // ---- GEMM2: m[h][k] = silu( eb2[h] + sum_o h1[o][k]*eW2[o][h] ) ----
    // split-o: half 0 -> o in [0,193), half 1 -> [193,386). 2 outputs x 6 k per thread.
    {
        const int h  = tid & 31;
        const int kg = (tid >> 5) & 7;
        const int half = tid >> 8;
        const int k0 = kg * 6;
        const int o0 = half * 193;
        u64 acc[2][3];
        #pragma unroll
        for (int oi = 0; oi < 2; oi++)
            #pragma unroll
            for (int j = 0; j < 3; j++) acc[oi][j] = 0ull;

        #pragma unroll 2
        for (int o = o0; o < o0 + 193; o++) {
            const u64* hp = (const u64*)(h1_s + o * 48 + k0);
            u64 a0 = hp[0], a1 = hp[1], a2 = hp[2];
            const float* wr = eW2 + o * 64 + h;
            u64 w0 = dup2(wr[0]), w1 = dup2(wr[32]);
            ffma2(acc[0][0], a0, w0); ffma2(acc[0][1], a1, w0); ffma2(acc[0][2], a2, w0);
            ffma2(acc[1][0], a0, w1); ffma2(acc[1][1], a1, w1); ffma2(acc[1][2], a2, w1);
        }
        float* part = h3_s;  // reuse as partial buffer
        if (half == 0) {
            #pragma unroll
            for (int oi = 0; oi < 2; oi++)
                #pragma unroll
                for (int j = 0; j < 3; j++)
                    *(u64*)(part + (h + 32 * oi) * 48 + k0 + 2 * j) = acc[oi][j];
        }
        __syncthreads();
        if (half == 1) {
            #pragma unroll
            for (int oi = 0; oi < 2; oi++) {
                int hh = h + 32 * oi;
                u64 bpack = dup2(eb2[hh]);
                #pragma unroll
                for (int j = 0; j < 3; j++) {
                    u64 t = addf2(addf2(acc[oi][j], *(u64*)(part + hh * 48 + k0 + 2 * j)), bpack);
                    float2 p = unpk(t);
                    *(float2*)(m_s + hh * 48 + k0 + 2 * j) = make_float2(siluf(p.x), siluf(p.y));
                }
            }
        }
    }
    __syncthreads();

    // ---- GEMM3: h3[g][k] = silu( hb1[g] + sum_h m[h][k]*hW1[h][g] ) ----
    // 4 outputs {g4, g4+64, g4+128, g4+192} x 6 k per thread
    {
        const int g4 = tid & 63;
        const int kg = tid >> 6;
        const int k0 = kg * 6;
        u64 acc[4][3];
        #pragma unroll
        for (int oi = 0; oi < 4; oi++) {
            u64 d = dup2(hb1[g4 + 64 * oi]);
            #pragma unroll
            for (int j = 0; j < 3; j++) acc[oi][j] = d;
        }
        #pragma unroll 2
        for (int h = 0; h < 64; h++) {
            const u64* mp = (const u64*)(m_s + h * 48 + k0);
            u64 a0 = mp[0], a1 = mp[1], a2 = mp[2];
            const float* wr = hW1 + h * H4_ + g4;
            #pragma unroll
            for (int oi = 0; oi < 4; oi++) {
                u64 w2 = dup2(wr[64 * oi]);
                ffma2(acc[oi][0], a0, w2); ffma2(acc[oi][1], a1, w2); ffma2(acc[oi][2], a2, w2);
            }
        }
        #pragma unroll
        for (int oi = 0; oi < 4; oi++) {
            float* dst = h3_s + (g4 + 64 * oi) * 48 + k0;
            #pragma unroll
            for (int j = 0; j < 3; j++) {
                float2 p = unpk(acc[oi][j]);
                *(float2*)(dst + 2 * j) = make_float2(siluf(p.x), siluf(p.y));
            }
        }
    }
    __syncthreads();

    // ---- GEMM4: htw[d][k] = hb2[d] + sum_g h3[g][k]*hW2[g][d] ----
    // split-g: half 0 -> g in [0,128), half 1 -> [128,256). 2 outputs x 6 k.
    {
        const int d  = tid & 31;
        const int kg = (tid >> 5) & 7;
        const int half = tid >> 8;
        const int k0 = kg * 6;
        const int g0 = half * 128;
        u64 acc[2][3];
        #pragma unroll
        for (int oi = 0; oi < 2; oi++)
            #pragma unroll
            for (int j = 0; j < 3; j++) acc[oi][j] = 0ull;

        #pragma unroll 2
        for (int g = g0; g < g0 + 128; g++) {
            const u64* hp = (const u64*)(h3_s + g * 48 + k0);
            u64 a0 = hp[0], a1 = hp[1], a2 = hp[2];
            const float* wr = hW2 + g * 64 + d;
            u64 w0 = dup2(wr[0]), w1 = dup2(wr[32]);
            ffma2(acc[0][0], a0, w0); ffma2(acc[0][1], a1, w0); ffma2(acc[0][2], a2, w0);
            ffma2(acc[1][0], a0, w1); ffma2(acc[1][1], a1, w1); ffma2(acc[1][2], a2, w1);
        }
        float* part = x_s;  // reuse x area as partial buffer
        if (half == 0) {
            #pragma unroll
            for (int oi = 0; oi < 2; oi++)
                #pragma unroll
                for (int j = 0; j < 3; j++)
                    *(u64*)(part + (d + 32 * oi) * 48 + k0 + 2 * j) = acc[oi][j];
        }
        __syncthreads();
        if (half == 1) {
            #pragma unroll
            for (int oi = 0; oi < 2; oi++) {
                int dd = d + 32 * oi;
                u64 bpack = dup2(hb2[dd]);
                #pragma unroll
                for (int j = 0; j < 3; j++) {
                    u64 t = addf2(addf2(acc[oi][j], *(u64*)(part + dd * 48 + k0 + 2 * j)), bpack);
                    *(u64*)(htw_s + dd * 48 + k0 + 2 * j) = t;
                }
            }
        }
    }
    __syncthreads();

    // ---- m_i = sum_k mask[k] * m_ij[h][k] ----
    {
        int h = tid & 63;
        int kb = tid >> 6;
        int k0 = kb * 6;
        float s = 0.f;
        #pragma unroll
        for (int kk = 0; kk < 6; kk++) s += msk_s[k0 + kk] * m_s[h * 48 + k0 + kk];
        red[kb * 64 + h] = s;
    }
    __syncthreads();
    if (tid < 64) {
        float s = 0.f;
        #pragma unroll
        for (int kb = 0; kb < 8; kb++) s += red[kb * 64 + tid];
        mi_s[tid] = s;
    }
    __syncthreads();

    // ---- ht_update einsum ----
    {
        int d = tid & 63;
        int kb = tid >> 6;
        int k0 = kb * 6;
        float a0 = 0.f, a1 = 0.f, a2 = 0.f;
        float sc = hns_s[d], bi = hnb_s[d];
        float h0 = hti[d * 3 + 0], h1v = hti[d * 3 + 1], h2 = hti[d * 3 + 2];
        #pragma unroll
        for (int kk = 0; kk < 6; kk++) {
            int k = k0 + kk;
            int j = base + idx_s[k];
            const float* hj = f1 + j * 192 + d * 3;
            float r0 = h0 - hj[0];
            float r1 = h1v - hj[1];
            float r2 = h2 - hj[2];
            float nrm = sqrtf(r0 * r0 + r1 * r1 + r2 * r2);
            float coef = (nrm * sc + bi) / fmaxf(nrm, 1e-8f);
            float w = coef * htw_s[d * 48 + k];
            a0 += r0 * w; a1 += r1 * w; a2 += r2 * w;
        }
        red[kb * 192 + d * 3 + 0] = a0;
        red[kb * 192 + d * 3 + 1] = a1;
        red[kb * 192 + d * 3 + 2] = a2;
    }
    __syncthreads();
    if (tid < 192) {
        float s = 0.f;
        #pragma unroll
        for (int kb = 0; kb < 8; kb++) s += red[kb * 192 + tid];
        htu_s[tid] = s;
    }
    __syncthreads();

    // ---- Node tail: LayerNorm -> MLP(128->128->64) + residual -> gate -> output ----
    if (tid < 32) {
        float s = ni_s[tid] + ni_s[tid + 32];
        #pragma unroll
        for (int off = 16; off > 0; off >>= 1) s += __shfl_xor_sync(0xffffffffu, s, off);
        if (tid == 0) stat[0] = s * (1.f / 64.f);
    }
    __syncthreads();
    if (tid < 32) {
        float mu = stat[0];
        float d0 = ni_s[tid] - mu, d1 = ni_s[tid + 32] - mu;
        float s = d0 * d0 + d1 * d1;
        #pragma unroll
        for (int off = 16; off > 0; off >>= 1) s += __shfl_xor_sync(0xffffffffu, s, off);
        if (tid == 0) stat[1] = s * (1.f / 64.f);
    }
    __syncthreads();
    if (tid < 64) {
        float mu = stat[0];
        float inv = rsqrtf(stat[1] + 1e-5f);
        nm[tid] = (ni_s[tid] - mu) * inv * ln_g[tid] + ln_b[tid];
        nm[64 + tid] = mi_s[tid];
    }
    __syncthreads();
    if (tid < 128) {
        float a = nb1[tid];
        #pragma unroll 8
        for (int e = 0; e < 128; e++) a += nm[e] * nW1[e * 128 + tid];
        hbuf[tid] = siluf(a);
    }
    __syncthreads();
    if (tid < 64) {
        float a = nb2[tid];
        #pragma unroll 8
        for (int g = 0; g < 128; g++) a += hbuf[g] * nW2[g * 64 + tid];
        no_s[tid] = a + ni_s[tid];
    }
    __syncthreads();
    if (tid < 64) {
        float a = gb[tid];
        #pragma unroll 8
        for (int e = 0; e < 64; e++) a += no_s[e] * gW[e * 64 + tid];
        float gate = __fdividef(1.f, 1.f + __expf(-a));
        int ob = node * 256 + tid * 4;
        out[ob + 0] = no_s[tid];
        #pragma unroll
        for (int m = 0; m < 3; m++)
            out[ob + 1 + m] = (hti[tid * 3 + m] + htu_s[tid * 3 + m]) * gate;
    }
}

extern "C" void kernel_launch(void* const* d_in, const int* in_sizes, int n_in,
                              void* d_out, int out_size)
{
    const float*         f0    = (const float*)d_in[0];
    const float*         f1    = (const float*)d_in[1];
    const float*         rd    = (const float*)d_in[2];
    const int*           nidx  = (const int*)d_in[3];
    const unsigned char* nmask = (const unsigned char*)d_in[4];
    const float* ln_g = (const float*)d_in[5];
    const float* ln_b = (const float*)d_in[6];
    const float* eW1  = (const float*)d_in[7];
    const float* eb1  = (const float*)d_in[8];
    const float* eW2  = (const float*)d_in[9];
    const float* eb2  = (const float*)d_in[10];
    const float* hW1  = (const float*)d_in[11];
    const float* hb1  = (const float*)d_in[12];
    const float* hW2  = (const float*)d_in[13];
    const float* hb2  = (const float*)d_in[14];
    const float* nW1  = (const float*)d_in[15];
    const float* nb1  = (const float*)d_in[16];
    const float* nW2  = (const float*)d_in[17];
    const float* nb2  = (const float*)d_in[18];
    const float* hns  = (const float*)d_in[19];
    const float* hnb  = (const float*)d_in[20];
    const float* gW   = (const float*)d_in[21];
    const float* gb   = (const float*)d_in[22];
    float* out = (float*)d_out;

    cudaFuncSetAttribute(fused_kernel, cudaFuncAttributeMaxDynamicSharedMemorySize,
                         SMEM_FLOATS * (int)sizeof(float));

    detect_mask_kernel<<<1, 1>>>((const unsigned int*)nmask);
    fused_kernel<<<B_ * N_, 512, SMEM_FLOATS * sizeof(float)>>>(
        f0, f1, rd, nidx, nmask, ln_g, ln_b, eW1, eb1, eW2, eb2,
        hW1, hb1, hW2, hb2, nW1, nb1, nW2, nb2, hns, hnb, gW, gb, out);
}

// round 9
// speedup vs baseline: 1.4321x; 1.2311x over previous
#include <cuda_runtime.h>
#include <math.h>

typedef unsigned long long u64;

// Problem constants
#define B_   2
#define N_   2048
#define K_   48
#define KC_  24     // k-chunk
#define D0_  64
#define D1_  64
#define H_   64
#define EIN_ 193
#define E2_  386    // 2*EIN
#define H4_  256    // 4*H

__device__ int g_mask_mode;  // 0=uint8, 1=int32, 2=float32

__global__ void detect_mask_kernel(const unsigned int* __restrict__ w) {
    bool int_ok = true, flt_ok = true;
    #pragma unroll 8
    for (int i = 0; i < 64; i++) {
        unsigned int v = w[i];
        if (v != 0u && v != 1u) int_ok = false;
        if (v != 0u && v != 0x3F800000u) flt_ok = false;
    }
    g_mask_mode = int_ok ? 1 : (flt_ok ? 2 : 0);
}

__device__ __forceinline__ float siluf(float v) {
    return v * __fdividef(1.f, 1.f + __expf(-v));
}
__device__ __forceinline__ u64 dup2(float w) {
    u64 r; asm("mov.b64 %0, {%1, %1};" : "=l"(r) : "f"(w)); return r;
}
__device__ __forceinline__ void ffma2(u64 &d, u64 a, u64 b) {
    asm("fma.rn.f32x2 %0, %1, %2, %0;" : "+l"(d) : "l"(a), "l"(b));
}
__device__ __forceinline__ u64 addf2(u64 a, u64 b) {
    u64 r; asm("add.rn.f32x2 %0, %1, %2;" : "=l"(r) : "l"(a), "l"(b)); return r;
}
__device__ __forceinline__ float2 unpk(u64 v) {
    float2 f; asm("mov.b64 {%0, %1}, %2;" : "=f"(f.x), "=f"(f.y) : "l"(v)); return f;
}

// Shared memory layout (floats) -- chunked (KC=24)
#define OFF_NI   0          // 64
#define OFF_HTI  64         // 192
#define OFF_HNS  256        // 64
#define OFF_HNB  320        // 64
#define OFF_MSK  384        // 48
#define OFF_IDX  432        // 48 ints
#define OFF_MI   480        // 64
#define OFF_HTU  544        // 192
#define OFF_NM   736        // 128
#define OFF_HB   864        // 128
#define OFF_NO   992        // 64
#define OFF_STAT 1056       // 2
#define OFF_C0   1058       // 386 (pad to even base: 1058 is even)
#define OFF_X    1448       // 129*24 = 3096   (reused as GEMM4 partial)
#define OFF_H1   4544       // 386*24 = 9264
#define OFF_M    13808      // 64*24 = 1536
#define OFF_H3   15344      // 256*24 = 6144   (first used as GEMM2 partials: 3*1536)
#define OFF_HTW  21488      // 64*24 = 1536
#define OFF_RED  23024      // 8*192 = 1536
#define SMEM_FLOATS 24560   // 98,240 bytes

__global__ __launch_bounds__(512, 2) void fused_kernel(
    const float* __restrict__ f0, const float* __restrict__ f1,
    const float* __restrict__ rd, const int* __restrict__ nidx,
    const unsigned char* __restrict__ nmask,
    const float* __restrict__ ln_g, const float* __restrict__ ln_b,
    const float* __restrict__ eW1, const float* __restrict__ eb1,
    const float* __restrict__ eW2, const float* __restrict__ eb2,
    const float* __restrict__ hW1, const float* __restrict__ hb1,
    const float* __restrict__ hW2, const float* __restrict__ hb2,
    const float* __restrict__ nW1, const float* __restrict__ nb1,
    const float* __restrict__ nW2, const float* __restrict__ nb2,
    const float* __restrict__ hns, const float* __restrict__ hnb,
    const float* __restrict__ gW, const float* __restrict__ gb,
    float* __restrict__ out)
{
    extern __shared__ float sm[];
    const int node = blockIdx.x;
    const int base = (node >> 11) << 11;
    const int tid = threadIdx.x;

    float* ni_s  = sm + OFF_NI;
    float* hti   = sm + OFF_HTI;
    float* hns_s = sm + OFF_HNS;
    float* hnb_s = sm + OFF_HNB;
    float* msk_s = sm + OFF_MSK;
    int*   idx_s = (int*)(sm + OFF_IDX);
    float* mi_s  = sm + OFF_MI;
    float* htu_s = sm + OFF_HTU;
    float* nm    = sm + OFF_NM;
    float* hbuf  = sm + OFF_HB;
    float* no_s  = sm + OFF_NO;
    float* stat  = sm + OFF_STAT;
    float* c0_s  = sm + OFF_C0;
    float* x_s   = sm + OFF_X;
    float* h1_s  = sm + OFF_H1;
    float* m_s   = sm + OFF_M;
    float* h3_s  = sm + OFF_H3;
    float* htw_s = sm + OFF_HTW;
    float* red   = sm + OFF_RED;

    // ---- Stage 0: per-node loads ----
    if (tid < 64) {
        ni_s[tid]  = f0[node * 64 + tid];
        hns_s[tid] = hns[tid];
        hnb_s[tid] = hnb[tid];
        mi_s[tid]  = 0.f;
    }
    if (tid >= 64 && tid < 256) {
        hti[tid - 64] = f1[node * 192 + (tid - 64)];
        htu_s[tid - 64] = 0.f;
    }
    if (tid >= 256 && tid < 304) {
        int k = tid - 256;
        idx_s[k] = nidx[node * 48 + k];
        int mode = g_mask_mode;
        float mv;
        if (mode == 1)      mv = ((const int*)nmask)[node * 48 + k] ? 1.f : 0.f;
        else if (mode == 2) mv = ((const float*)nmask)[node * 48 + k];
        else                mv = nmask[node * 48 + k] ? 1.f : 0.f;
        msk_s[k] = mv;
    }
    __syncthreads();

    // ---- c0[o] = eb1[o] + nodes_i . eW1[0:64,o]  (once per block) ----
    if (tid < E2_) {
        float c = eb1[tid];
        #pragma unroll 8
        for (int i = 0; i < 64; i++) c += ni_s[i] * eW1[i * E2_ + tid];
        c0_s[tid] = c;
    }
    // (c0_s consumed after the next __syncthreads inside the chunk loop)

    for (int c = 0; c < 2; c++) {
        const int kbase = c * KC_;

        // ---- Stage 1: build x rows for this chunk ----
        for (int e = tid; e < KC_ * 64; e += 512) {
            int k = e / 64, d = e % 64;
            int j = base + idx_s[kbase + k];
            x_s[d * KC_ + k] = f0[j * 64 + d];
            const float* hj = f1 + j * 192 + d * 3;
            float r0 = hti[d * 3 + 0] - hj[0];
            float r1 = hti[d * 3 + 1] - hj[1];
            float r2 = hti[d * 3 + 2] - hj[2];
            x_s[(64 + d) * KC_ + k] = sqrtf(r0 * r0 + r1 * r1 + r2 * r2);
        }
        if (tid < KC_) x_s[128 * KC_ + tid] = rd[node * 48 + kbase + tid];
        __syncthreads();

        // ---- GEMM1: h1[o][k] = silu( c0[o] + sum_i x[i][k]*eW1[64+i][o] ) ----
        // ob in [0,128), 3(+1) outputs; kb in [0,4), 6 k each (3 packed)
        {
            const int ob = tid & 127;
            const int k0 = (tid >> 7) * 6;
            const bool has4 = (ob < 2);

            u64 acc[3][3], acc4[3];
            #pragma unroll
            for (int oi = 0; oi < 3; oi++) {
                u64 d = dup2(c0_s[ob + oi * 128]);
                acc[oi][0] = d; acc[oi][1] = d; acc[oi][2] = d;
            }
            {
                u64 d = has4 ? dup2(c0_s[ob + 384]) : 0ull;
                acc4[0] = d; acc4[1] = d; acc4[2] = d;
            }

            const float* xb = x_s + k0;
            for (int i = 0; i < 129; i++) {
                const u64* xr = (const u64*)(xb + i * KC_);
                u64 a0 = xr[0], a1 = xr[1], a2 = xr[2];
                const float* wr = eW1 + (64 + i) * E2_ + ob;
                #pragma unroll
                for (int oi = 0; oi < 3; oi++) {
                    u64 w2 = dup2(wr[oi * 128]);
                    ffma2(acc[oi][0], a0, w2);
                    ffma2(acc[oi][1], a1, w2);
                    ffma2(acc[oi][2], a2, w2);
                }
                if (has4) {
                    u64 w2 = dup2(wr[384]);
                    ffma2(acc4[0], a0, w2);
                    ffma2(acc4[1], a1, w2);
                    ffma2(acc4[2], a2, w2);
                }
            }

            #pragma unroll
            for (int oi = 0; oi < 3; oi++) {
                float* dst = h1_s + (ob + oi * 128) * KC_ + k0;
                #pragma unroll
                for (int j = 0; j < 3; j++) {
                    float2 p = unpk(acc[oi][j]);
                    *(float2*)(dst + 2 * j) = make_float2(siluf(p.x), siluf(p.y));
                }
            }
            if (has4) {
                float* dst = h1_s + (ob + 384) * KC_ + k0;
                #pragma unroll
                for (int j = 0; j < 3; j++) {
                    float2 p = unpk(acc4[j]);
                    *(float2*)(dst + 2 * j) = make_float2(siluf(p.x), siluf(p.y));
                }
            }
        }
        __syncthreads();

        // ---- GEMM2: m[h][k] = silu( eb2[h] + sum_o h1[o][k]*eW2[o][h] ) ----
        // 4-way split over o: oq ranges {0:97, 97:194, 194:290, 290:386}
        {
            const int oq = tid >> 7;
            const int h  = tid & 31;
            const int k0 = ((tid >> 5) & 3) * 6;
            const int o_start = (oq == 0) ? 0 : (oq == 1 ? 97 : (oq == 2 ? 194 : 290));
            const int o_end   = (oq == 0) ? 97 : (oq == 1 ? 194 : (oq == 2 ? 290 : 386));

            u64 acc[2][3];
            #pragma unroll
            for (int oi = 0; oi < 2; oi++) { acc[oi][0] = 0; acc[oi][1] = 0; acc[oi][2] = 0; }

            for (int o = o_start; o < o_end; o++) {
                const u64* hp = (const u64*)(h1_s + o * KC_ + k0);
                u64 a0 = hp[0], a1 = hp[1], a2 = hp[2];
                const float* wr = eW2 + o * 64 + h;
                u64 w0 = dup2(wr[0]), w1 = dup2(wr[32]);
                ffma2(acc[0][0], a0, w0); ffma2(acc[0][1], a1, w0); ffma2(acc[0][2], a2, w0);
                ffma2(acc[1][0], a0, w1); ffma2(acc[1][1], a1, w1); ffma2(acc[1][2], a2, w1);
            }
            if (oq > 0) {
                float* part = h3_s + (oq - 1) * 1536;
                #pragma unroll
                for (int oi = 0; oi < 2; oi++)
                    #pragma unroll
                    for (int j = 0; j < 3; j++)
                        *(u64*)(part + (h + 32 * oi) * KC_ + k0 + 2 * j) = acc[oi][j];
            }
            __syncthreads();
            if (oq == 0) {
                #pragma unroll
                for (int oi = 0; oi < 2; oi++) {
                    int hh = h + 32 * oi;
                    u64 bpack = dup2(eb2[hh]);
                    #pragma unroll
                    for (int j = 0; j < 3; j++) {
                        u64 t = acc[oi][j];
                        t = addf2(t, *(u64*)(h3_s + 0 * 1536 + hh * KC_ + k0 + 2 * j));
                        t = addf2(t, *(u64*)(h3_s + 1 * 1536 + hh * KC_ + k0 + 2 * j));
                        t = addf2(t, *(u64*)(h3_s + 2 * 1536 + hh * KC_ + k0 + 2 * j));
                        t = addf2(t, bpack);
                        float2 p = unpk(t);
                        *(float2*)(m_s + hh * KC_ + k0 + 2 * j) = make_float2(siluf(p.x), siluf(p.y));
                    }
                }
            }
        }
        __syncthreads();

        // ---- GEMM3: h3[g][k] = silu( hb1[g] + sum_h m[h][k]*hW1[h][g] ) ----
        // g in [0,128), outputs {g, g+128}; kb in [0,4)
        {
            const int g  = tid & 127;
            const int k0 = (tid >> 7) * 6;
            u64 acc[2][3];
            #pragma unroll
            for (int oi = 0; oi < 2; oi++) {
                u64 d = dup2(hb1[g + 128 * oi]);
                acc[oi][0] = d; acc[oi][1] = d; acc[oi][2] = d;
            }
            #pragma unroll 2
            for (int h = 0; h < 64; h++) {
                const u64* mp = (const u64*)(m_s + h * KC_ + k0);
                u64 a0 = mp[0], a1 = mp[1], a2 = mp[2];
                const float* wr = hW1 + h * H4_ + g;
                u64 w0 = dup2(wr[0]), w1 = dup2(wr[128]);
                ffma2(acc[0][0], a0, w0); ffma2(acc[0][1], a1, w0); ffma2(acc[0][2], a2, w0);
                ffma2(acc[1][0], a0, w1); ffma2(acc[1][1], a1, w1); ffma2(acc[1][2], a2, w1);
            }
            #pragma unroll
            for (int oi = 0; oi < 2; oi++) {
                float* dst = h3_s + (g + 128 * oi) * KC_ + k0;
                #pragma unroll
                for (int j = 0; j < 3; j++) {
                    float2 p = unpk(acc[oi][j]);
                    *(float2*)(dst + 2 * j) = make_float2(siluf(p.x), siluf(p.y));
                }
            }
        }
        __syncthreads();

        // ---- GEMM4: htw[d][k] = hb2[d] + sum_g h3[g][k]*hW2[g][d] ----
        // split-g halves; d in [0,32), outputs {d, d+32}; kb in [0,4)
        {
            const int half = tid >> 8;
            const int d  = tid & 31;
            const int k0 = ((tid >> 5) & 3) * 6;
            const int g0 = half * 128;
            u64 acc[2][3];
            #pragma unroll
            for (int oi = 0; oi < 2; oi++) { acc[oi][0] = 0; acc[oi][1] = 0; acc[oi][2] = 0; }

            #pragma unroll 2
            for (int g = g0; g < g0 + 128; g++) {
                const u64* hp = (const u64*)(h3_s + g * KC_ + k0);
                u64 a0 = hp[0], a1 = hp[1], a2 = hp[2];
                const float* wr = hW2 + g * 64 + d;
                u64 w0 = dup2(wr[0]), w1 = dup2(wr[32]);
                ffma2(acc[0][0], a0, w0); ffma2(acc[0][1], a1, w0); ffma2(acc[0][2], a2, w0);
                ffma2(acc[1][0], a0, w1); ffma2(acc[1][1], a1, w1); ffma2(acc[1][2], a2, w1);
            }
            if (half == 0) {
                #pragma unroll
                for (int oi = 0; oi < 2; oi++)
                    #pragma unroll
                    for (int j = 0; j < 3; j++)
                        *(u64*)(x_s + (d + 32 * oi) * KC_ + k0 + 2 * j) = acc[oi][j];
            }
            __syncthreads();
            if (half == 1) {
                #pragma unroll
                for (int oi = 0; oi < 2; oi++) {
                    int dd = d + 32 * oi;
                    u64 bpack = dup2(hb2[dd]);
                    #pragma unroll
                    for (int j = 0; j < 3; j++) {
                        u64 t = addf2(addf2(acc[oi][j],
                                 *(u64*)(x_s + dd * KC_ + k0 + 2 * j)), bpack);
                        *(u64*)(htw_s + dd * KC_ + k0 + 2 * j) = t;
                    }
                }
            }
        }
        __syncthreads();

        // ---- m_i accumulation (masked sum over this chunk's k) ----
        {
            int h = tid & 63;
            int kb = tid >> 6;
            int k0 = kb * 3;
            float s = 0.f;
            #pragma unroll
            for (int kk = 0; kk < 3; kk++)
                s += msk_s[kbase + k0 + kk] * m_s[h * KC_ + k0 + kk];
            red[kb * 64 + h] = s;
        }
        __syncthreads();
        if (tid < 64) {
            float s = 0.f;
            #pragma unroll
            for (int kb = 0; kb < 8; kb++) s += red[kb * 64 + tid];
            mi_s[tid] += s;
        }
        __syncthreads();

        // ---- ht_update einsum for this chunk ----
        {
            int d = tid & 63;
            int kb = tid >> 6;
            int k0 = kb * 3;
            float a0 = 0.f, a1 = 0.f, a2 = 0.f;
            float sc = hns_s[d], bi = hnb_s[d];
            float h0 = hti[d * 3 + 0], h1v = hti[d * 3 + 1], h2 = hti[d * 3 + 2];
            #pragma unroll
            for (int kk = 0; kk < 3; kk++) {
                int k = k0 + kk;
                int j = base + idx_s[kbase + k];
                const float* hj = f1 + j * 192 + d * 3;
                float r0 = h0 - hj[0];
                float r1 = h1v - hj[1];
                float r2 = h2 - hj[2];
                float nrm = sqrtf(r0 * r0 + r1 * r1 + r2 * r2);
                float coef = (nrm * sc + bi) / fmaxf(nrm, 1e-8f);
                float w = coef * htw_s[d * KC_ + k];
                a0 += r0 * w; a1 += r1 * w; a2 += r2 * w;
            }
            red[kb * 192 + d * 3 + 0] = a0;
            red[kb * 192 + d * 3 + 1] = a1;
            red[kb * 192 + d * 3 + 2] = a2;
        }
        __syncthreads();
        if (tid < 192) {
            float s = 0.f;
            #pragma unroll
            for (int kb = 0; kb < 8; kb++) s += red[kb * 192 + tid];
            htu_s[tid] += s;
        }
        __syncthreads();
    }

    // ---- Node tail: LayerNorm -> MLP(128->128->64) + residual -> gate -> output ----
    if (tid < 32) {
        float s = ni_s[tid] + ni_s[tid + 32];
        #pragma unroll
        for (int off = 16; off > 0; off >>= 1) s += __shfl_xor_sync(0xffffffffu, s, off);
        if (tid == 0) stat[0] = s * (1.f / 64.f);
    }
    __syncthreads();
    if (tid < 32) {
        float mu = stat[0];
        float d0 = ni_s[tid] - mu, d1 = ni_s[tid + 32] - mu;
        float s = d0 * d0 + d1 * d1;
        #pragma unroll
        for (int off = 16; off > 0; off >>= 1) s += __shfl_xor_sync(0xffffffffu, s, off);
        if (tid == 0) stat[1] = s * (1.f / 64.f);
    }
    __syncthreads();
    if (tid < 64) {
        float mu = stat[0];
        float inv = rsqrtf(stat[1] + 1e-5f);
        nm[tid] = (ni_s[tid] - mu) * inv * ln_g[tid] + ln_b[tid];
        nm[64 + tid] = mi_s[tid];
    }
    __syncthreads();
    if (tid < 128) {
        float a = nb1[tid];
        #pragma unroll 8
        for (int e = 0; e < 128; e++) a += nm[e] * nW1[e * 128 + tid];
        hbuf[tid] = siluf(a);
    }
    __syncthreads();
    if (tid < 64) {
        float a = nb2[tid];
        #pragma unroll 8
        for (int g = 0; g < 128; g++) a += hbuf[g] * nW2[g * 64 + tid];
        no_s[tid] = a + ni_s[tid];
    }
    __syncthreads();
    if (tid < 64) {
        float a = gb[tid];
        #pragma unroll 8
        for (int e = 0; e < 64; e++) a += no_s[e] * gW[e * 64 + tid];
        float gate = __fdividef(1.f, 1.f + __expf(-a));
        int ob = node * 256 + tid * 4;
        out[ob + 0] = no_s[tid];
        #pragma unroll
        for (int m = 0; m < 3; m++)
            out[ob + 1 + m] = (hti[tid * 3 + m] + htu_s[tid * 3 + m]) * gate;
    }
}

extern "C" void kernel_launch(void* const* d_in, const int* in_sizes, int n_in,
                              void* d_out, int out_size)
{
    const float*         f0    = (const float*)d_in[0];
    const float*         f1    = (const float*)d_in[1];
    const float*         rd    = (const float*)d_in[2];
    const int*           nidx  = (const int*)d_in[3];
    const unsigned char* nmask = (const unsigned char*)d_in[4];
    const float* ln_g = (const float*)d_in[5];
    const float* ln_b = (const float*)d_in[6];
    const float* eW1  = (const float*)d_in[7];
    const float* eb1  = (const float*)d_in[8];
    const float* eW2  = (const float*)d_in[9];
    const float* eb2  = (const float*)d_in[10];
    const float* hW1  = (const float*)d_in[11];
    const float* hb1  = (const float*)d_in[12];
    const float* hW2  = (const float*)d_in[13];
    const float* hb2  = (const float*)d_in[14];
    const float* nW1  = (const float*)d_in[15];
    const float* nb1  = (const float*)d_in[16];
    const float* nW2  = (const float*)d_in[17];
    const float* nb2  = (const float*)d_in[18];
    const float* hns  = (const float*)d_in[19];
    const float* hnb  = (const float*)d_in[20];
    const float* gW   = (const float*)d_in[21];
    const float* gb   = (const float*)d_in[22];
    float* out = (float*)d_out;

    cudaFuncSetAttribute(fused_kernel, cudaFuncAttributeMaxDynamicSharedMemorySize,
                         SMEM_FLOATS * (int)sizeof(float));

    detect_mask_kernel<<<1, 1>>>((const unsigned int*)nmask);
    fused_kernel<<<B_ * N_, 512, SMEM_FLOATS * sizeof(float)>>>(
        f0, f1, rd, nidx, nmask, ln_g, ln_b, eW1, eb1, eW2, eb2,
        hW1, hb1, hW2, hb2, nW1, nb1, nW2, nb2, hns, hnb, gW, gb, out);
}